// round 16
// baseline (speedup 1.0000x reference)
#include <cuda_runtime.h>
#include <cstdint>

#define V_NUM 80000
#define P_NUM 20
#define C_OUT 64
#define NY 640
#define NX 640
#define B_NUM 4

static constexpr float BN_EPS = 0.001f;
static constexpr size_t PLANE  = (size_t)NY * NX;                 // 409600
static constexpr size_t CANVAS = (size_t)B_NUM * C_OUT * PLANE;   // 104857600
static constexpr int    MAP_N  = B_NUM * NY * NX;                 // 1638400

__device__ __constant__ float kVX   = 100.0f / 640.0f;
__device__ __constant__ float kXOFF = 100.0f / 640.0f * 0.5f - 50.0f;

// Zero-initialized device scratch; self-validation (g_pix[g_map[pix]] == pix)
// makes per-call clearing unnecessary.
__device__ float  g_feats[(size_t)V_NUM * C_OUT];  // 20.5 MB
__device__ int    g_map[MAP_N];                    // pixel -> voxel id
__device__ int    g_pix[V_NUM];                    // voxel id -> pixel
// Folded per-channel constants, paired (c, c+32):
// rows: 0:A 1:B 2:C 3:D 4:bb 5..9: sw4..sw8
__device__ float2 g_fold[10 * 32];

// ---------------------------------------------------------------------------
// Kernel 0: fold BN + weight sums once (1 warp). [R4 / 102.5us config]
// ---------------------------------------------------------------------------
__global__ void fold_kernel(const float* __restrict__ W,
                            const float* __restrict__ gamma,
                            const float* __restrict__ beta,
                            const float* __restrict__ rmean,
                            const float* __restrict__ rvar)
{
    const int t = threadIdx.x;           // 0..31
    if (t >= 32) return;
    const int c0 = t, c1 = t + 32;

    const float s0 = rsqrtf(rvar[c0] + BN_EPS) * gamma[c0];
    const float s1 = rsqrtf(rvar[c1] + BN_EPS) * gamma[c1];
    const float bb0 = beta[c0] - rmean[c0] * s0;
    const float bb1 = beta[c1] - rmean[c1] * s1;

    float sw0[9], sw1[9];
    #pragma unroll
    for (int i = 0; i < 9; i++) {
        sw0[i] = W[i * C_OUT + c0] * s0;
        sw1[i] = W[i * C_OUT + c1] * s1;
    }
    g_fold[0 * 32 + t] = make_float2(sw0[0] + sw0[4] + sw0[7],
                                     sw1[0] + sw1[4] + sw1[7]);   // A
    g_fold[1 * 32 + t] = make_float2(sw0[1] + sw0[5] + sw0[8],
                                     sw1[1] + sw1[5] + sw1[8]);   // B
    g_fold[2 * 32 + t] = make_float2(sw0[2] + sw0[6],
                                     sw1[2] + sw1[6]);            // C
    g_fold[3 * 32 + t] = make_float2(sw0[3], sw1[3]);             // D
    g_fold[4 * 32 + t] = make_float2(bb0, bb1);                   // bb
    #pragma unroll
    for (int i = 0; i < 5; i++)
        g_fold[(5 + i) * 32 + t] = make_float2(sw0[4 + i], sw1[4 + i]);
}

// ---------------------------------------------------------------------------
// Kernel 1: per-voxel features -> g_feats, id <-> pixel links.
// [R4 / 102.5us config verbatim: one warp per voxel, 128-thr blocks,
//  gmem fold loads issued at warp start, shuffle mean, masked FMA loop]
// ---------------------------------------------------------------------------
__global__ void __launch_bounds__(128)
compute_feats_kernel(const float* __restrict__ voxels,
                     const int*   __restrict__ num_points,
                     const int*   __restrict__ coors)
{
    const int v = blockIdx.x * (blockDim.x >> 5) + (threadIdx.x >> 5);
    if (v >= V_NUM) return;
    const int lane = threadIdx.x & 31;

    const float4* __restrict__ vox =
        reinterpret_cast<const float4*>(voxels) + (size_t)v * P_NUM;

    int npv = num_points[v];
    npv = npv < 0 ? 0 : (npv > P_NUM ? P_NUM : npv);

    // folded channel constants (coalesced LDG.64, issue immediately)
    const float2 A  = g_fold[0 * 32 + lane];
    const float2 B  = g_fold[1 * 32 + lane];
    const float2 C  = g_fold[2 * 32 + lane];
    const float2 D  = g_fold[3 * 32 + lane];
    const float2 bb = g_fold[4 * 32 + lane];
    const float2 s4 = g_fold[5 * 32 + lane];
    const float2 s5 = g_fold[6 * 32 + lane];
    const float2 s6 = g_fold[7 * 32 + lane];
    const float2 s7 = g_fold[8 * 32 + lane];
    const float2 s8 = g_fold[9 * 32 + lane];

    // mean over valid points via warp reduction
    float sx = 0.f, sy = 0.f, sz = 0.f;
    if (lane < npv) {
        float4 pt = vox[lane];
        sx = pt.x; sy = pt.y; sz = pt.z;
    }
    #pragma unroll
    for (int o = 16; o; o >>= 1) {
        sx += __shfl_xor_sync(0xffffffffu, sx, o);
        sy += __shfl_xor_sync(0xffffffffu, sy, o);
        sz += __shfl_xor_sync(0xffffffffu, sz, o);
    }
    const float inv_n = 1.0f / (float)(npv > 1 ? npv : 1);
    const float mx = sx * inv_n, my = sy * inv_n, mz = sz * inv_n;

    const int b  = coors[v * 4 + 0];
    const int yy = coors[v * 4 + 2];
    const int xx = coors[v * 4 + 3];
    const float cx = (float)xx * kVX + kXOFF;
    const float cy = (float)yy * kVX + kXOFF;

    // per-voxel constant term
    const float E0 = bb.x - (mx * s4.x + my * s5.x + mz * s6.x
                           + cx * s7.x + cy * s8.x);
    const float E1 = bb.y - (mx * s4.y + my * s5.y + mz * s6.y
                           + cx * s7.y + cy * s8.y);

    // masked (zero-feature) points contribute relu(BN bias) to the max
    float m0 = (npv < P_NUM) ? fmaxf(bb.x, 0.0f) : -3.4e38f;
    float m1 = (npv < P_NUM) ? fmaxf(bb.y, 0.0f) : -3.4e38f;

    for (int p = 0; p < npv; p++) {
        const float4 pt = vox[p];
        float h0 = fmaf(pt.x, A.x, E0);
        float h1 = fmaf(pt.x, A.y, E1);
        h0 = fmaf(pt.y, B.x, h0);   h1 = fmaf(pt.y, B.y, h1);
        h0 = fmaf(pt.z, C.x, h0);   h1 = fmaf(pt.z, C.y, h1);
        h0 = fmaf(pt.w, D.x, h0);   h1 = fmaf(pt.w, D.y, h1);
        m0 = fmaxf(m0, fmaxf(h0, 0.0f));
        m1 = fmaxf(m1, fmaxf(h1, 0.0f));
    }

    g_feats[(size_t)v * C_OUT + lane]      = m0;
    g_feats[(size_t)v * C_OUT + lane + 32] = m1;
    if (lane == 0) {
        const int pix = b * (NY * NX) + yy * NX + xx;
        g_map[pix] = v;
        g_pix[v]   = pix;
    }
}

// ---------------------------------------------------------------------------
// Kernel 2: coalesced render of canvas + occ. Proven geometry (256 thr,
// 512B smem, 12800 blocks). SINGLE CHANGE vs the 102.5us run: plain
// write-back stores instead of __stcs — let L2 aggregate full lines and
// drain in long bursts (memset-like) rather than eager streaming evicts.
// Gather inputs (~27MB) still fit L2 alongside the write stream.
// ---------------------------------------------------------------------------
__global__ void __launch_bounds__(256)
render_kernel(float* __restrict__ out)
{
    __shared__ int map_s[128];

    const int b  = blockIdx.z;
    const int y  = blockIdx.y;
    const int x0 = blockIdx.x * 128;
    const int t  = threadIdx.x;

    const int pix_base = b * (NY * NX) + y * NX + x0;
    if (t < 128) {
        const int pix = pix_base + t;
        int v = g_map[pix];
        if (g_pix[v] != pix) v = -1;   // stale / zero-init -> invalid
        map_s[t] = v;
    }
    __syncthreads();

    const int xq  = (t & 31) * 4;
    const int row = t >> 5;            // 0..7

    const int v0 = map_s[xq + 0];
    const int v1 = map_s[xq + 1];
    const int v2 = map_s[xq + 2];
    const int v3 = map_s[xq + 3];

    const size_t out_xbase = (size_t)y * NX + x0 + xq;

    #pragma unroll
    for (int k = 0; k < 8; k++) {
        const int c = row + k * 8;
        float4 val = make_float4(0.f, 0.f, 0.f, 0.f);
        if (v0 >= 0) val.x = g_feats[(size_t)v0 * C_OUT + c];
        if (v1 >= 0) val.y = g_feats[(size_t)v1 * C_OUT + c];
        if (v2 >= 0) val.z = g_feats[(size_t)v2 * C_OUT + c];
        if (v3 >= 0) val.w = g_feats[(size_t)v3 * C_OUT + c];
        float4* dst = reinterpret_cast<float4*>(
            out + ((size_t)(b * C_OUT + c)) * PLANE + out_xbase);
        *dst = val;                    // write-back store (L2 aggregation)
    }

    if (t < 32) {
        float4 occ = make_float4(v0 >= 0 ? 1.f : 0.f,
                                 v1 >= 0 ? 1.f : 0.f,
                                 v2 >= 0 ? 1.f : 0.f,
                                 v3 >= 0 ? 1.f : 0.f);
        float4* dst = reinterpret_cast<float4*>(
            out + CANVAS + (size_t)b * PLANE + out_xbase);
        *dst = occ;
    }
}

extern "C" void kernel_launch(void* const* d_in, const int* in_sizes, int n_in,
                              void* d_out, int out_size)
{
    const float* voxels     = (const float*)d_in[0];
    const int*   num_points = (const int*)  d_in[1];
    const int*   coors      = (const int*)  d_in[2];
    const float* W          = (const float*)d_in[3];
    const float* gamma      = (const float*)d_in[4];
    const float* beta       = (const float*)d_in[5];
    const float* rmean      = (const float*)d_in[6];
    const float* rvar       = (const float*)d_in[7];
    float* out = (float*)d_out;

    fold_kernel<<<1, 32>>>(W, gamma, beta, rmean, rvar);

    compute_feats_kernel<<<(V_NUM + 3) / 4, 128>>>(voxels, num_points, coors);

    dim3 grid(NX / 128, NY, B_NUM);
    render_kernel<<<grid, 256>>>(out);
}

// round 17
// speedup vs baseline: 1.1524x; 1.1524x over previous
#include <cuda_runtime.h>
#include <cstdint>

#define V_NUM 80000
#define P_NUM 20
#define C_OUT 64
#define NY 640
#define NX 640
#define B_NUM 4

static constexpr float BN_EPS = 0.001f;
static constexpr size_t PLANE  = (size_t)NY * NX;                 // 409600
static constexpr size_t CANVAS = (size_t)B_NUM * C_OUT * PLANE;   // 104857600
static constexpr int    MAP_N  = B_NUM * NY * NX;                 // 1638400

__device__ __constant__ float kVX   = 100.0f / 640.0f;
__device__ __constant__ float kXOFF = 100.0f / 640.0f * 0.5f - 50.0f;

// Zero-initialized device scratch; self-validation (g_pix[g_map[pix]] == pix)
// makes per-call clearing unnecessary.
__device__ float  g_feats[(size_t)V_NUM * C_OUT];  // 20.5 MB
__device__ int    g_map[MAP_N];                    // pixel -> voxel id
__device__ int    g_pix[V_NUM];                    // voxel id -> pixel
// Folded per-channel constants, paired (c, c+32):
// rows: 0:A 1:B 2:C 3:D 4:bb 5..9: sw4..sw8
__device__ float2 g_fold[10 * 32];

// ---------------------------------------------------------------------------
// Kernel 0: fold BN + weight sums once (1 warp).
// [Banked optimum: separate launch beats every in-kernel fold variant.]
// ---------------------------------------------------------------------------
__global__ void fold_kernel(const float* __restrict__ W,
                            const float* __restrict__ gamma,
                            const float* __restrict__ beta,
                            const float* __restrict__ rmean,
                            const float* __restrict__ rvar)
{
    const int t = threadIdx.x;           // 0..31
    if (t >= 32) return;
    const int c0 = t, c1 = t + 32;

    const float s0 = rsqrtf(rvar[c0] + BN_EPS) * gamma[c0];
    const float s1 = rsqrtf(rvar[c1] + BN_EPS) * gamma[c1];
    const float bb0 = beta[c0] - rmean[c0] * s0;
    const float bb1 = beta[c1] - rmean[c1] * s1;

    float sw0[9], sw1[9];
    #pragma unroll
    for (int i = 0; i < 9; i++) {
        sw0[i] = W[i * C_OUT + c0] * s0;
        sw1[i] = W[i * C_OUT + c1] * s1;
    }
    g_fold[0 * 32 + t] = make_float2(sw0[0] + sw0[4] + sw0[7],
                                     sw1[0] + sw1[4] + sw1[7]);   // A
    g_fold[1 * 32 + t] = make_float2(sw0[1] + sw0[5] + sw0[8],
                                     sw1[1] + sw1[5] + sw1[8]);   // B
    g_fold[2 * 32 + t] = make_float2(sw0[2] + sw0[6],
                                     sw1[2] + sw1[6]);            // C
    g_fold[3 * 32 + t] = make_float2(sw0[3], sw1[3]);             // D
    g_fold[4 * 32 + t] = make_float2(bb0, bb1);                   // bb
    #pragma unroll
    for (int i = 0; i < 5; i++)
        g_fold[(5 + i) * 32 + t] = make_float2(sw0[4 + i], sw1[4 + i]);
}

// ---------------------------------------------------------------------------
// Kernel 1: per-voxel features -> g_feats, id <-> pixel links.
// [Banked optimum: one warp per voxel, 128-thr blocks, gmem fold loads
//  issued at warp start (full MLP), shuffle mean, masked FMA loop.]
// ---------------------------------------------------------------------------
__global__ void __launch_bounds__(128)
compute_feats_kernel(const float* __restrict__ voxels,
                     const int*   __restrict__ num_points,
                     const int*   __restrict__ coors)
{
    const int v = blockIdx.x * (blockDim.x >> 5) + (threadIdx.x >> 5);
    if (v >= V_NUM) return;
    const int lane = threadIdx.x & 31;

    const float4* __restrict__ vox =
        reinterpret_cast<const float4*>(voxels) + (size_t)v * P_NUM;

    int npv = num_points[v];
    npv = npv < 0 ? 0 : (npv > P_NUM ? P_NUM : npv);

    // folded channel constants (coalesced LDG.64, issue immediately)
    const float2 A  = g_fold[0 * 32 + lane];
    const float2 B  = g_fold[1 * 32 + lane];
    const float2 C  = g_fold[2 * 32 + lane];
    const float2 D  = g_fold[3 * 32 + lane];
    const float2 bb = g_fold[4 * 32 + lane];
    const float2 s4 = g_fold[5 * 32 + lane];
    const float2 s5 = g_fold[6 * 32 + lane];
    const float2 s6 = g_fold[7 * 32 + lane];
    const float2 s7 = g_fold[8 * 32 + lane];
    const float2 s8 = g_fold[9 * 32 + lane];

    // mean over valid points via warp reduction
    float sx = 0.f, sy = 0.f, sz = 0.f;
    if (lane < npv) {
        float4 pt = vox[lane];
        sx = pt.x; sy = pt.y; sz = pt.z;
    }
    #pragma unroll
    for (int o = 16; o; o >>= 1) {
        sx += __shfl_xor_sync(0xffffffffu, sx, o);
        sy += __shfl_xor_sync(0xffffffffu, sy, o);
        sz += __shfl_xor_sync(0xffffffffu, sz, o);
    }
    const float inv_n = 1.0f / (float)(npv > 1 ? npv : 1);
    const float mx = sx * inv_n, my = sy * inv_n, mz = sz * inv_n;

    const int b  = coors[v * 4 + 0];
    const int yy = coors[v * 4 + 2];
    const int xx = coors[v * 4 + 3];
    const float cx = (float)xx * kVX + kXOFF;
    const float cy = (float)yy * kVX + kXOFF;

    // per-voxel constant term
    const float E0 = bb.x - (mx * s4.x + my * s5.x + mz * s6.x
                           + cx * s7.x + cy * s8.x);
    const float E1 = bb.y - (mx * s4.y + my * s5.y + mz * s6.y
                           + cx * s7.y + cy * s8.y);

    // masked (zero-feature) points contribute relu(BN bias) to the max
    float m0 = (npv < P_NUM) ? fmaxf(bb.x, 0.0f) : -3.4e38f;
    float m1 = (npv < P_NUM) ? fmaxf(bb.y, 0.0f) : -3.4e38f;

    for (int p = 0; p < npv; p++) {
        const float4 pt = vox[p];
        float h0 = fmaf(pt.x, A.x, E0);
        float h1 = fmaf(pt.x, A.y, E1);
        h0 = fmaf(pt.y, B.x, h0);   h1 = fmaf(pt.y, B.y, h1);
        h0 = fmaf(pt.z, C.x, h0);   h1 = fmaf(pt.z, C.y, h1);
        h0 = fmaf(pt.w, D.x, h0);   h1 = fmaf(pt.w, D.y, h1);
        m0 = fmaxf(m0, fmaxf(h0, 0.0f));
        m1 = fmaxf(m1, fmaxf(h1, 0.0f));
    }

    g_feats[(size_t)v * C_OUT + lane]      = m0;
    g_feats[(size_t)v * C_OUT + lane + 32] = m1;
    if (lane == 0) {
        const int pix = b * (NY * NX) + yy * NX + xx;
        g_map[pix] = v;
        g_pix[v]   = pix;
    }
}

// ---------------------------------------------------------------------------
// Kernel 2: coalesced render of canvas + occ.
// [Banked optimum: 256 thr, 512B smem, 32 regs, 12800 blocks, 94% occ,
//  ~62% DRAM — the measured ceiling for this scatter-gather+strided-write
//  pattern. __stcs is load-bearing: write-back costs +15us (R16).]
// ---------------------------------------------------------------------------
__global__ void __launch_bounds__(256)
render_kernel(float* __restrict__ out)
{
    __shared__ int map_s[128];

    const int b  = blockIdx.z;
    const int y  = blockIdx.y;
    const int x0 = blockIdx.x * 128;
    const int t  = threadIdx.x;

    const int pix_base = b * (NY * NX) + y * NX + x0;
    if (t < 128) {
        const int pix = pix_base + t;
        int v = g_map[pix];
        if (g_pix[v] != pix) v = -1;   // stale / zero-init -> invalid
        map_s[t] = v;
    }
    __syncthreads();

    const int xq  = (t & 31) * 4;
    const int row = t >> 5;            // 0..7

    const int v0 = map_s[xq + 0];
    const int v1 = map_s[xq + 1];
    const int v2 = map_s[xq + 2];
    const int v3 = map_s[xq + 3];

    const size_t out_xbase = (size_t)y * NX + x0 + xq;

    #pragma unroll
    for (int k = 0; k < 8; k++) {
        const int c = row + k * 8;
        float4 val = make_float4(0.f, 0.f, 0.f, 0.f);
        if (v0 >= 0) val.x = g_feats[(size_t)v0 * C_OUT + c];
        if (v1 >= 0) val.y = g_feats[(size_t)v1 * C_OUT + c];
        if (v2 >= 0) val.z = g_feats[(size_t)v2 * C_OUT + c];
        if (v3 >= 0) val.w = g_feats[(size_t)v3 * C_OUT + c];
        float4* dst = reinterpret_cast<float4*>(
            out + ((size_t)(b * C_OUT + c)) * PLANE + out_xbase);
        __stcs(dst, val);              // streaming store: eager ordered drain
    }

    if (t < 32) {
        float4 occ = make_float4(v0 >= 0 ? 1.f : 0.f,
                                 v1 >= 0 ? 1.f : 0.f,
                                 v2 >= 0 ? 1.f : 0.f,
                                 v3 >= 0 ? 1.f : 0.f);
        float4* dst = reinterpret_cast<float4*>(
            out + CANVAS + (size_t)b * PLANE + out_xbase);
        __stcs(dst, occ);
    }
}

extern "C" void kernel_launch(void* const* d_in, const int* in_sizes, int n_in,
                              void* d_out, int out_size)
{
    const float* voxels     = (const float*)d_in[0];
    const int*   num_points = (const int*)  d_in[1];
    const int*   coors      = (const int*)  d_in[2];
    const float* W          = (const float*)d_in[3];
    const float* gamma      = (const float*)d_in[4];
    const float* beta       = (const float*)d_in[5];
    const float* rmean      = (const float*)d_in[6];
    const float* rvar       = (const float*)d_in[7];
    float* out = (float*)d_out;

    fold_kernel<<<1, 32>>>(W, gamma, beta, rmean, rvar);

    compute_feats_kernel<<<(V_NUM + 3) / 4, 128>>>(voxels, num_points, coors);

    dim3 grid(NX / 128, NY, B_NUM);
    render_kernel<<<grid, 256>>>(out);
}